// round 1
// baseline (speedup 1.0000x reference)
#include <cuda_runtime.h>
#include <cuda_bf16.h>

// AlphaModel: per-edge elementwise over N=4M edges, P=3.
// Inputs (metadata order):
//   0 prnt_probs  [N,3] f32
//   1 child_probs [N,3] f32
//   2 rel_mu      [20,3,3] f32
//   3 rel_sigma   [20,3,3] f32
//   4 eps_M       [N,3,3] f32
//   5 beta        [N] f32
//   6 rels        [N] i32
// Output (assumed flattened tuple concat, f32, 8N elements):
//   [0,N)   copy_mask (0/1)
//   [N,4N)  child_probs2copy [N,3]
//   [4N,5N) alpha_mask (0/1)
//   [5N,8N) alpha [N,3]

__global__ __launch_bounds__(256)
void alpha_kernel(const float* __restrict__ prnt,
                  const float* __restrict__ child,
                  const float* __restrict__ rel_mu,
                  const float* __restrict__ rel_sigma,
                  const float* __restrict__ eps,
                  const float* __restrict__ beta,
                  const int*  __restrict__ rels,
                  float* __restrict__ out,
                  int nq, int n)
{
    // Stage rel params in smem, rows padded 9->12 floats so each 3x3 matrix
    // reads as 3 aligned LDS.128.
    __shared__ float smu[20 * 12];
    __shared__ float ssg[20 * 12];
    for (int j = threadIdx.x; j < 180; j += blockDim.x) {
        int r = j / 9, k = j % 9;
        smu[r * 12 + k] = rel_mu[j];
        ssg[r * 12 + k] = rel_sigma[j];
    }
    __syncthreads();

    int t = blockIdx.x * blockDim.x + threadIdx.x;
    if (t >= nq) return;

    // Batched vector loads: this thread owns edges 4t .. 4t+3.
    float p[12], c[12], ev[36], bv[4];
    int   rv[4];
    {
        const float4* p4 = (const float4*)prnt;
        const float4* c4 = (const float4*)child;
        const float4* e4 = (const float4*)eps;
        #pragma unroll
        for (int i = 0; i < 3; i++) ((float4*)p)[i] = p4[3 * t + i];
        #pragma unroll
        for (int i = 0; i < 3; i++) ((float4*)c)[i] = c4[3 * t + i];
        #pragma unroll
        for (int i = 0; i < 9; i++) ((float4*)ev)[i] = e4[9 * t + i];
        *(float4*)bv = ((const float4*)beta)[t];
        *(int4*)rv   = ((const int4*)rels)[t];
    }

    float o_cm[4], o_am[4], o_cc[12], o_al[12];

    #pragma unroll
    for (int k = 0; k < 4; k++) {
        const float p0 = p[3*k+0], p1 = p[3*k+1], p2 = p[3*k+2];
        const float c0 = c[3*k+0], c1 = c[3*k+1], c2 = c[3*k+2];
        const float* eg = ev + 9 * k;
        const int r = rv[k];

        float mrow[12], srow[12];
        #pragma unroll
        for (int i = 0; i < 3; i++) {
            ((float4*)mrow)[i] = *(const float4*)(smu + r * 12 + 4 * i);
            ((float4*)srow)[i] = *(const float4*)(ssg + r * 12 + 4 * i);
        }

        // logits = (mu + sigma*eps) @ child   (fused: 6 FFMA per row)
        float l0 = 0.f, l1 = 0.f, l2 = 0.f;
        {
            l0 = fmaf(fmaf(srow[0], eg[0], mrow[0]), c0, l0);
            l0 = fmaf(fmaf(srow[1], eg[1], mrow[1]), c1, l0);
            l0 = fmaf(fmaf(srow[2], eg[2], mrow[2]), c2, l0);
            l1 = fmaf(fmaf(srow[3], eg[3], mrow[3]), c0, l1);
            l1 = fmaf(fmaf(srow[4], eg[4], mrow[4]), c1, l1);
            l1 = fmaf(fmaf(srow[5], eg[5], mrow[5]), c2, l1);
            l2 = fmaf(fmaf(srow[6], eg[6], mrow[6]), c0, l2);
            l2 = fmaf(fmaf(srow[7], eg[7], mrow[7]), c1, l2);
            l2 = fmaf(fmaf(srow[8], eg[8], mrow[8]), c2, l2);
        }

        // softmax (max-subtracted; logits are O(10) so this is belt+braces)
        float mx = fmaxf(l0, fmaxf(l1, l2));
        float x0 = __expf(l0 - mx), x1 = __expf(l1 - mx), x2 = __expf(l2 - mx);
        float inv = __fdividef(1.f, x0 + x1 + x2);
        float q0 = x0 * inv, q1 = x1 * inv, q2 = x2 * inv;   // cp

        float csum = c0 + c1 + c2;
        float psum = p0 + p1 + p2;
        bool cm    = (csum != 0.f);
        bool pz    = (psum == 0.f);
        bool copym = cm && pz;
        bool am    = cm && !pz;

        // scale(prnt, cp)
        float z0 = fmaxf(0.01f, p0 + q0);
        float z1 = fmaxf(0.01f, p1 + q1);
        float z2 = fmaxf(0.01f, p2 + q2);
        float izs = __fdividef(1.f, z0 + z1 + z2);
        z0 *= izs; z1 *= izs; z2 *= izs;
        float H = -(z0 * __logf(z0) + z1 * __logf(z1) + z2 * __logf(z2));

        float dotv = p0 * q0 + p1 * q1 + p2 * q2;
        float sqp  = p0 * p0 + p1 * p1 + p2 * p2;
        float sqc  = q0 * q0 + q1 * q1 + q2 * q2;
        float den  = sqp * sqc;
        // safe_norm semantics: if either norm is 0, divide by 1.
        float cosv = (den == 0.f) ? dotv : dotv * rsqrtf(den);
        cosv = fmaxf(0.01f, cosv);
        float s = __fdividef(42.f * cosv, H);

        float b  = bv[k];
        float sa = am ? s : 0.f;   // fold alpha mask into the scale
        o_al[3*k+0] = fmaf(b, q0 - p0, p0) * sa;
        o_al[3*k+1] = fmaf(b, q1 - p1, p1) * sa;
        o_al[3*k+2] = fmaf(b, q2 - p2, p2) * sa;
        o_cc[3*k+0] = copym ? q0 : 0.f;
        o_cc[3*k+1] = copym ? q1 : 0.f;
        o_cc[3*k+2] = copym ? q2 : 0.f;
        o_cm[k] = copym ? 1.f : 0.f;
        o_am[k] = am ? 1.f : 0.f;
    }

    // Vector stores. All four output sections are 16MB-multiple offsets from
    // the 256B-aligned d_out base, so float4 stores stay aligned.
    float4* ocm = (float4*)(out);
    float4* occ = (float4*)(out + (size_t)n);
    float4* oam = (float4*)(out + (size_t)4 * n);
    float4* oal = (float4*)(out + (size_t)5 * n);
    ocm[t] = *(float4*)o_cm;
    oam[t] = *(float4*)o_am;
    #pragma unroll
    for (int i = 0; i < 3; i++) occ[3 * t + i] = ((float4*)o_cc)[i];
    #pragma unroll
    for (int i = 0; i < 3; i++) oal[3 * t + i] = ((float4*)o_al)[i];
}

extern "C" void kernel_launch(void* const* d_in, const int* in_sizes, int n_in,
                              void* d_out, int out_size) {
    const float* prnt      = (const float*)d_in[0];
    const float* child     = (const float*)d_in[1];
    const float* rel_mu    = (const float*)d_in[2];
    const float* rel_sigma = (const float*)d_in[3];
    const float* eps       = (const float*)d_in[4];
    const float* beta      = (const float*)d_in[5];
    const int*   rels      = (const int*)d_in[6];
    const int n  = in_sizes[5];   // beta element count == N (4,000,000; divisible by 4)
    const int nq = n / 4;
    const int block = 256;
    const int grid  = (nq + block - 1) / block;
    alpha_kernel<<<grid, block>>>(prnt, child, rel_mu, rel_sigma, eps, beta, rels,
                                  (float*)d_out, nq, n);
}

// round 4
// speedup vs baseline: 1.0321x; 1.0321x over previous
#include <cuda_runtime.h>
#include <cuda_bf16.h>

// AlphaModel: per-edge elementwise over N=4M edges, P=3. HBM-bound:
// ~400MB mandatory traffic -> ~62us floor at ~6.4TB/s achievable.
// R2 change: allow 128 regs/thread (was 63 w/ spills) so all 17 input
// LDG.128 stay register-resident -> no LDL/STL spill traffic, MLP=17.
//
// Inputs (metadata order):
//   0 prnt_probs  [N,3] f32
//   1 child_probs [N,3] f32
//   2 rel_mu      [20,3,3] f32
//   3 rel_sigma   [20,3,3] f32
//   4 eps_M       [N,3,3] f32
//   5 beta        [N] f32
//   6 rels        [N] i32
// Output f32, 8N: [copy_mask N | cp2copy 3N | alpha_mask N | alpha 3N]

__global__ __launch_bounds__(256, 2)
void alpha_kernel(const float* __restrict__ prnt,
                  const float* __restrict__ child,
                  const float* __restrict__ rel_mu,
                  const float* __restrict__ rel_sigma,
                  const float* __restrict__ eps,
                  const float* __restrict__ beta,
                  const int*  __restrict__ rels,
                  float* __restrict__ out,
                  int nq, int n)
{
    // Stage rel params in smem, rows padded 9->12 floats so each 3x3 matrix
    // reads as 3 aligned LDS.128.
    __shared__ float smu[20 * 12];
    __shared__ float ssg[20 * 12];
    for (int j = threadIdx.x; j < 180; j += blockDim.x) {
        int r = j / 9, k = j % 9;
        smu[r * 12 + k] = rel_mu[j];
        ssg[r * 12 + k] = rel_sigma[j];
    }
    __syncthreads();

    int t = blockIdx.x * blockDim.x + threadIdx.x;
    if (t >= nq) return;

    // Front-batch all input loads: 17 LDG.128 in flight per thread.
    float p[12], c[12], ev[36], bv[4];
    int   rv[4];
    {
        const float4* p4 = (const float4*)prnt;
        const float4* c4 = (const float4*)child;
        const float4* e4 = (const float4*)eps;
        #pragma unroll
        for (int i = 0; i < 3; i++) ((float4*)p)[i] = p4[3 * t + i];
        #pragma unroll
        for (int i = 0; i < 3; i++) ((float4*)c)[i] = c4[3 * t + i];
        #pragma unroll
        for (int i = 0; i < 9; i++) ((float4*)ev)[i] = e4[9 * t + i];
        *(float4*)bv = ((const float4*)beta)[t];
        *(int4*)rv   = ((const int4*)rels)[t];
    }

    float o_cm[4], o_am[4], o_cc[12], o_al[12];

    #pragma unroll
    for (int k = 0; k < 4; k++) {
        const float p0 = p[3*k+0], p1 = p[3*k+1], p2 = p[3*k+2];
        const float c0 = c[3*k+0], c1 = c[3*k+1], c2 = c[3*k+2];
        const float* eg = ev + 9 * k;
        const float* mrow = smu + rv[k] * 12;
        const float* srow = ssg + rv[k] * 12;

        // logits = (mu + sigma*eps) @ child   (LDS feeds FFMA directly)
        float l0, l1, l2;
        l0  = fmaf(srow[0], eg[0], mrow[0]) * c0;
        l0 += fmaf(srow[1], eg[1], mrow[1]) * c1;
        l0  = fmaf(fmaf(srow[2], eg[2], mrow[2]), c2, l0);
        l1  = fmaf(srow[3], eg[3], mrow[3]) * c0;
        l1 += fmaf(srow[4], eg[4], mrow[4]) * c1;
        l1  = fmaf(fmaf(srow[5], eg[5], mrow[5]), c2, l1);
        l2  = fmaf(srow[6], eg[6], mrow[6]) * c0;
        l2 += fmaf(srow[7], eg[7], mrow[7]) * c1;
        l2  = fmaf(fmaf(srow[8], eg[8], mrow[8]), c2, l2);

        // softmax (max-subtracted)
        float mx = fmaxf(l0, fmaxf(l1, l2));
        float x0 = __expf(l0 - mx), x1 = __expf(l1 - mx), x2 = __expf(l2 - mx);
        float inv = __fdividef(1.f, x0 + x1 + x2);
        float q0 = x0 * inv, q1 = x1 * inv, q2 = x2 * inv;   // cp

        float csum = c0 + c1 + c2;
        float psum = p0 + p1 + p2;
        bool cm    = (csum != 0.f);
        bool pz    = (psum == 0.f);
        bool copym = cm && pz;
        bool am    = cm && !pz;

        // scale(prnt, cp)
        float z0 = fmaxf(0.01f, p0 + q0);
        float z1 = fmaxf(0.01f, p1 + q1);
        float z2 = fmaxf(0.01f, p2 + q2);
        float izs = __fdividef(1.f, z0 + z1 + z2);
        z0 *= izs; z1 *= izs; z2 *= izs;
        float H = -(z0 * __logf(z0) + z1 * __logf(z1) + z2 * __logf(z2));

        float dotv = p0 * q0 + p1 * q1 + p2 * q2;
        float sqp  = p0 * p0 + p1 * p1 + p2 * p2;
        float sqc  = q0 * q0 + q1 * q1 + q2 * q2;
        float den  = sqp * sqc;
        // safe_norm semantics: if either norm is 0, divide by 1.
        float cosv = (den == 0.f) ? dotv : dotv * rsqrtf(den);
        cosv = fmaxf(0.01f, cosv);

        float b  = bv[k];
        // fold alpha mask into the scale
        float sa = am ? __fdividef(42.f * cosv, H) : 0.f;
        o_al[3*k+0] = fmaf(b, q0 - p0, p0) * sa;
        o_al[3*k+1] = fmaf(b, q1 - p1, p1) * sa;
        o_al[3*k+2] = fmaf(b, q2 - p2, p2) * sa;
        o_cc[3*k+0] = copym ? q0 : 0.f;
        o_cc[3*k+1] = copym ? q1 : 0.f;
        o_cc[3*k+2] = copym ? q2 : 0.f;
        o_cm[k] = copym ? 1.f : 0.f;
        o_am[k] = am ? 1.f : 0.f;
    }

    // Vector stores; all section offsets are multiples of 4 floats.
    float4* ocm = (float4*)(out);
    float4* occ = (float4*)(out + (size_t)n);
    float4* oam = (float4*)(out + (size_t)4 * n);
    float4* oal = (float4*)(out + (size_t)5 * n);
    ocm[t] = *(float4*)o_cm;
    oam[t] = *(float4*)o_am;
    #pragma unroll
    for (int i = 0; i < 3; i++) occ[3 * t + i] = ((float4*)o_cc)[i];
    #pragma unroll
    for (int i = 0; i < 3; i++) oal[3 * t + i] = ((float4*)o_al)[i];
}

extern "C" void kernel_launch(void* const* d_in, const int* in_sizes, int n_in,
                              void* d_out, int out_size) {
    const float* prnt      = (const float*)d_in[0];
    const float* child     = (const float*)d_in[1];
    const float* rel_mu    = (const float*)d_in[2];
    const float* rel_sigma = (const float*)d_in[3];
    const float* eps       = (const float*)d_in[4];
    const float* beta      = (const float*)d_in[5];
    const int*   rels      = (const int*)d_in[6];
    const int n  = in_sizes[5];   // N = 4,000,000 (divisible by 4)
    const int nq = n / 4;
    const int block = 256;
    const int grid  = (nq + block - 1) / block;
    alpha_kernel<<<grid, block>>>(prnt, child, rel_mu, rel_sigma, eps, beta, rels,
                                  (float*)d_out, nq, n);
}

// round 9
// speedup vs baseline: 1.2170x; 1.1791x over previous
#include <cuda_runtime.h>
#include <cuda_bf16.h>

// AlphaModel: per-edge elementwise over N=4M edges, P=3. HBM-bound:
// ~400MB mandatory traffic -> ~60-62us floor.
// R5: 2 edges/thread (was 4) + launch_bounds(256,4) -> 64-reg budget,
// 32 warps/SM. R4 showed the limiter is warp concurrency (occ 22%,
// DRAM 65%), not spills or instruction count. float2 loads/stores keep
// alignment (24B/edge-pair stride is 8B-aligned, not 16B).
//
// Inputs (metadata order):
//   0 prnt_probs  [N,3] f32
//   1 child_probs [N,3] f32
//   2 rel_mu      [20,3,3] f32
//   3 rel_sigma   [20,3,3] f32
//   4 eps_M       [N,3,3] f32
//   5 beta        [N] f32
//   6 rels        [N] i32
// Output f32, 8N: [copy_mask N | cp2copy 3N | alpha_mask N | alpha 3N]

__global__ __launch_bounds__(256, 4)
void alpha_kernel(const float* __restrict__ prnt,
                  const float* __restrict__ child,
                  const float* __restrict__ rel_mu,
                  const float* __restrict__ rel_sigma,
                  const float* __restrict__ eps,
                  const float* __restrict__ beta,
                  const int*  __restrict__ rels,
                  float* __restrict__ out,
                  int nh, int n)
{
    // Stage rel params in smem, rows padded 9->12 floats so each 3x3 matrix
    // reads as 3 aligned LDS.128.
    __shared__ float smu[20 * 12];
    __shared__ float ssg[20 * 12];
    for (int j = threadIdx.x; j < 180; j += blockDim.x) {
        int r = j / 9, k = j % 9;
        smu[r * 12 + k] = rel_mu[j];
        ssg[r * 12 + k] = rel_sigma[j];
    }
    __syncthreads();

    int t = blockIdx.x * blockDim.x + threadIdx.x;
    if (t >= nh) return;

    // This thread owns edges 2t and 2t+1. All strides are 8B-aligned.
    float p[6], c[6], ev[18], bv[2];
    int   rv[2];
    {
        const float2* p2 = (const float2*)prnt;
        const float2* c2 = (const float2*)child;
        const float2* e2 = (const float2*)eps;
        #pragma unroll
        for (int i = 0; i < 3; i++) ((float2*)p)[i] = p2[3 * t + i];
        #pragma unroll
        for (int i = 0; i < 3; i++) ((float2*)c)[i] = c2[3 * t + i];
        #pragma unroll
        for (int i = 0; i < 9; i++) ((float2*)ev)[i] = e2[9 * t + i];
        *(float2*)bv = ((const float2*)beta)[t];
        *(int2*)rv   = ((const int2*)rels)[t];
    }

    float o_cm[2], o_am[2], o_cc[6], o_al[6];

    #pragma unroll
    for (int k = 0; k < 2; k++) {
        const float p0 = p[3*k+0], p1 = p[3*k+1], p2v = p[3*k+2];
        const float c0 = c[3*k+0], c1 = c[3*k+1], c2v = c[3*k+2];
        const float* eg = ev + 9 * k;
        const float* mrow = smu + rv[k] * 12;
        const float* srow = ssg + rv[k] * 12;

        // logits = (mu + sigma*eps) @ child
        float l0, l1, l2;
        l0  = fmaf(srow[0], eg[0], mrow[0]) * c0;
        l0 += fmaf(srow[1], eg[1], mrow[1]) * c1;
        l0  = fmaf(fmaf(srow[2], eg[2], mrow[2]), c2v, l0);
        l1  = fmaf(srow[3], eg[3], mrow[3]) * c0;
        l1 += fmaf(srow[4], eg[4], mrow[4]) * c1;
        l1  = fmaf(fmaf(srow[5], eg[5], mrow[5]), c2v, l1);
        l2  = fmaf(srow[6], eg[6], mrow[6]) * c0;
        l2 += fmaf(srow[7], eg[7], mrow[7]) * c1;
        l2  = fmaf(fmaf(srow[8], eg[8], mrow[8]), c2v, l2);

        // softmax (max-subtracted)
        float mx = fmaxf(l0, fmaxf(l1, l2));
        float x0 = __expf(l0 - mx), x1 = __expf(l1 - mx), x2 = __expf(l2 - mx);
        float inv = __fdividef(1.f, x0 + x1 + x2);
        float q0 = x0 * inv, q1 = x1 * inv, q2 = x2 * inv;   // cp

        float csum = c0 + c1 + c2v;
        float psum = p0 + p1 + p2v;
        bool cm    = (csum != 0.f);
        bool pz    = (psum == 0.f);
        bool copym = cm && pz;
        bool am    = cm && !pz;

        // scale(prnt, cp)
        float z0 = fmaxf(0.01f, p0 + q0);
        float z1 = fmaxf(0.01f, p1 + q1);
        float z2 = fmaxf(0.01f, p2v + q2);
        float izs = __fdividef(1.f, z0 + z1 + z2);
        z0 *= izs; z1 *= izs; z2 *= izs;
        float H = -(z0 * __logf(z0) + z1 * __logf(z1) + z2 * __logf(z2));

        float dotv = p0 * q0 + p1 * q1 + p2v * q2;
        float sqp  = p0 * p0 + p1 * p1 + p2v * p2v;
        float sqc  = q0 * q0 + q1 * q1 + q2 * q2;
        float den  = sqp * sqc;
        // safe_norm semantics: if either norm is 0, divide by 1.
        float cosv = (den == 0.f) ? dotv : dotv * rsqrtf(den);
        cosv = fmaxf(0.01f, cosv);

        float b  = bv[k];
        // fold alpha mask into the scale
        float sa = am ? __fdividef(42.f * cosv, H) : 0.f;
        o_al[3*k+0] = fmaf(b, q0 - p0, p0) * sa;
        o_al[3*k+1] = fmaf(b, q1 - p1, p1) * sa;
        o_al[3*k+2] = fmaf(b, q2 - p2v, p2v) * sa;
        o_cc[3*k+0] = copym ? q0 : 0.f;
        o_cc[3*k+1] = copym ? q1 : 0.f;
        o_cc[3*k+2] = copym ? q2 : 0.f;
        o_cm[k] = copym ? 1.f : 0.f;
        o_am[k] = am ? 1.f : 0.f;
    }

    // float2 stores; all section bases are multiples of 8 bytes.
    float2* ocm = (float2*)(out);
    float2* occ = (float2*)(out + (size_t)n);
    float2* oam = (float2*)(out + (size_t)4 * n);
    float2* oal = (float2*)(out + (size_t)5 * n);
    ocm[t] = *(float2*)o_cm;
    oam[t] = *(float2*)o_am;
    #pragma unroll
    for (int i = 0; i < 3; i++) occ[3 * t + i] = ((float2*)o_cc)[i];
    #pragma unroll
    for (int i = 0; i < 3; i++) oal[3 * t + i] = ((float2*)o_al)[i];
}

extern "C" void kernel_launch(void* const* d_in, const int* in_sizes, int n_in,
                              void* d_out, int out_size) {
    const float* prnt      = (const float*)d_in[0];
    const float* child     = (const float*)d_in[1];
    const float* rel_mu    = (const float*)d_in[2];
    const float* rel_sigma = (const float*)d_in[3];
    const float* eps       = (const float*)d_in[4];
    const float* beta      = (const float*)d_in[5];
    const int*   rels      = (const int*)d_in[6];
    const int n  = in_sizes[5];   // N = 4,000,000 (divisible by 2)
    const int nh = n / 2;
    const int block = 256;
    const int grid  = (nh + block - 1) / block;
    alpha_kernel<<<grid, block>>>(prnt, child, rel_mu, rel_sigma, eps, beta, rels,
                                  (float*)d_out, nh, n);
}